// round 4
// baseline (speedup 1.0000x reference)
#include <cuda_runtime.h>
#include <cmath>

#define BB 4
#define NN 2048
#define FF 128
#define HH 4
#define DD 32
#define MSPLIT 8
#define CROWS 64
#define MT 64

// ---------------- scratch (no allocations allowed) ----------------
__device__ float  g_h[BB * NN * FF];                 // 4 MB: h = x @ W^T
__device__ float4 g_src[BB * NN * HH];               // (e_src, exp(e_src), exp(0.2 e_src), 0)
__device__ float4 g_dst[BB * NN * HH];               // (e_dst, exp(e_dst), exp(0.2 e_dst), 0)
__device__ float  g_num[MSPLIT * BB * NN * FF];      // 33.5 MB partial numerators
__device__ float  g_den[MSPLIT * BB * NN * HH];      // partial denominators

// ---------------- Kernel A: h = x @ W^T  (8192 x 128 @ 128 x 128) ----------------
// 64 rows per CTA, 256 threads. W (128x132-padded) + x tile (64x132-padded) in smem.
// Thread (r = tid>>2, c = tid&3) computes outputs o = 4k + c, k = 0..31.
#define A_SMEM ((128 * 132 + 64 * 132) * 4)

__global__ void __launch_bounds__(256) k_gemm(const float* __restrict__ x,
                                              const float* __restrict__ W) {
    extern __shared__ float sm[];
    float* shW = sm;              // [128][132]
    float* shX = sm + 128 * 132;  // [64][132]
    const int tid = threadIdx.x;
    const int row0 = blockIdx.x * 64;

    #pragma unroll
    for (int t = 0; t < 16; t++) {                 // 128*32 float4 chunks
        int idx = tid + t * 256;
        int o = idx >> 5, i4 = idx & 31;
        float4 v = ((const float4*)W)[o * 32 + i4];
        *((float4*)(shW + o * 132 + 4 * i4)) = v;
    }
    #pragma unroll
    for (int t = 0; t < 8; t++) {                  // 64*32 float4 chunks
        int idx = tid + t * 256;
        int r = idx >> 5, i4 = idx & 31;
        float4 v = ((const float4*)x)[(size_t)(row0 + r) * 32 + i4];
        *((float4*)(shX + r * 132 + 4 * i4)) = v;
    }
    __syncthreads();

    const int r = tid >> 2, c = tid & 3;
    float acc[32];
    #pragma unroll
    for (int k = 0; k < 32; k++) acc[k] = 0.f;

    #pragma unroll 4
    for (int i4 = 0; i4 < 32; i4++) {
        float4 xv = *((const float4*)(shX + r * 132 + 4 * i4));
        #pragma unroll
        for (int k = 0; k < 32; k++) {
            int o = 4 * k + c;
            float4 wv = *((const float4*)(shW + o * 132 + 4 * i4));
            acc[k] = fmaf(xv.x, wv.x, acc[k]);
            acc[k] = fmaf(xv.y, wv.y, acc[k]);
            acc[k] = fmaf(xv.z, wv.z, acc[k]);
            acc[k] = fmaf(xv.w, wv.w, acc[k]);
        }
    }
    float* hrow = g_h + (size_t)(row0 + r) * FF;
    #pragma unroll
    for (int k = 0; k < 32; k++) hrow[4 * k + c] = acc[k];
}

// ---------------- Kernel B: per-(b,n,h) edge terms + factored exps ----------------
__global__ void __launch_bounds__(256) k_edge(const float* __restrict__ a_src,
                                              const float* __restrict__ a_dst) {
    int idx = blockIdx.x * 256 + threadIdx.x;      // (bn*H + h)
    if (idx >= BB * NN * HH) return;
    int h = idx & 3;
    int bn = idx >> 2;
    const float* hp = g_h + (size_t)bn * FF + h * DD;
    const float* as = a_src + h * DD;
    const float* ad = a_dst + h * DD;
    float es = 0.f, ed = 0.f;
    #pragma unroll
    for (int d = 0; d < DD; d++) {
        float v = hp[d];
        es = fmaf(v, as[d], es);
        ed = fmaf(v, ad[d], ed);
    }
    g_src[idx] = make_float4(es, expf(es), expf(0.2f * es), 0.f);
    g_dst[idx] = make_float4(ed, expf(ed), expf(0.2f * ed), 0.f);
}

// ---------------- Kernel C: fused masked-softmax aggregation (partials) ----------------
// grid (N/CROWS=32, B=4, MSPLIT=8), 256 threads.
// Thread (rg = tid>>3, c = tid&7) owns 2 rows x 16 cols. h tile is XOR-swizzled
// (chunk q stored at q ^ ((q>>3)&7)) so the stride-4-chunk read pattern per
// quarter-warp covers 8 distinct bank groups -> conflict-free LDS.128.
#define C_SMEM ((MT * FF + MT * HH * 4 + CROWS * (MT + 1)) * 4)

__global__ void __launch_bounds__(256) k_attn(const int* __restrict__ adj) {
    extern __shared__ float sm[];
    float*  sh_h   = sm;                          // [MT][128] swizzled
    float4* sh_e   = (float4*)(sm + MT * FF);     // [MT][HH]
    float*  sh_adj = sm + MT * FF + MT * HH * 4;  // [CROWS][MT+1]

    const int tid  = threadIdx.x;
    const int c    = tid & 7;
    const int rg   = tid >> 3;
    const int b    = blockIdx.y;
    const int z    = blockIdx.z;
    const int n0   = blockIdx.x * CROWS;
    const int na   = n0 + 2 * rg;
    const int head = c >> 1;

    const float4 spa = g_src[(size_t)(b * NN + na) * HH + head];
    const float4 spb = g_src[(size_t)(b * NN + na + 1) * HH + head];

    float acc[32];
    #pragma unroll
    for (int k = 0; k < 32; k++) acc[k] = 0.f;
    float dena = 0.f, denb = 0.f;

    const float4* hbase = (const float4*)(g_h + (size_t)b * NN * FF);
    const float4* ebase = g_dst + (size_t)b * NN * HH;

    const int m_begin = z * (NN / MSPLIT);
    const int m_end   = m_begin + (NN / MSPLIT);

    for (int m0 = m_begin; m0 < m_end; m0 += MT) {
        __syncthreads();
        // h tile: 2048 float4 chunks, swizzled placement
        #pragma unroll
        for (int t = 0; t < 8; t++) {
            int gidx = tid + t * 256;
            int j = gidx >> 5;
            int q = gidx & 31;
            int qs = q ^ ((q >> 3) & 7);
            ((float4*)sh_h)[j * 32 + qs] = hbase[(size_t)m0 * 32 + gidx];
        }
        // e_dst tile: [j][h] float4, 256 chunks
        sh_e[tid] = ebase[m0 * HH + tid];
        // adj tile (as float), padded rows to kill bank conflicts
        #pragma unroll
        for (int t = 0; t < 16; t++) {
            int gi = tid + t * 256;
            int rr = gi >> 6;
            int jj = gi & 63;
            sh_adj[rr * (MT + 1) + jj] =
                (float)adj[(size_t)(n0 + rr) * NN + m0 + jj];
        }
        __syncthreads();

        #pragma unroll 2
        for (int j = 0; j < MT; j++) {
            float4 ep = sh_e[j * HH + head];
            float aja = sh_adj[(2 * rg) * (MT + 1) + j];
            float ajb = sh_adj[(2 * rg + 1) * (MT + 1) + j];
            float za = spa.x + ep.x;
            float zb = spb.x + ep.x;
            float wa = ((za > 0.f) ? spa.y * ep.y : spa.z * ep.z) * aja;
            float wb = ((zb > 0.f) ? spb.y * ep.y : spb.z * ep.z) * ajb;
            dena += wa;
            denb += wb;
            #pragma unroll
            for (int s = 0; s < 4; s++) {
                int q = 4 * c + s;
                int qs = q ^ ((q >> 3) & 7);
                float4 hv = ((const float4*)sh_h)[j * 32 + qs];
                acc[4 * s + 0] = fmaf(wa, hv.x, acc[4 * s + 0]);
                acc[4 * s + 1] = fmaf(wa, hv.y, acc[4 * s + 1]);
                acc[4 * s + 2] = fmaf(wa, hv.z, acc[4 * s + 2]);
                acc[4 * s + 3] = fmaf(wa, hv.w, acc[4 * s + 3]);
                acc[16 + 4 * s + 0] = fmaf(wb, hv.x, acc[16 + 4 * s + 0]);
                acc[16 + 4 * s + 1] = fmaf(wb, hv.y, acc[16 + 4 * s + 1]);
                acc[16 + 4 * s + 2] = fmaf(wb, hv.z, acc[16 + 4 * s + 2]);
                acc[16 + 4 * s + 3] = fmaf(wb, hv.w, acc[16 + 4 * s + 3]);
            }
        }
    }

    size_t obase = (size_t)z * (BB * NN * FF);
    float4* numa = (float4*)(g_num + obase + (size_t)(b * NN + na) * FF + 16 * c);
    float4* numb = (float4*)(g_num + obase + (size_t)(b * NN + na + 1) * FF + 16 * c);
    #pragma unroll
    for (int s = 0; s < 4; s++) {
        numa[s] = make_float4(acc[4 * s], acc[4 * s + 1], acc[4 * s + 2], acc[4 * s + 3]);
        numb[s] = make_float4(acc[16 + 4 * s], acc[16 + 4 * s + 1],
                              acc[16 + 4 * s + 2], acc[16 + 4 * s + 3]);
    }
    if ((c & 1) == 0) {
        g_den[(size_t)z * (BB * NN * HH) + (size_t)(b * NN + na) * HH + head]     = dena;
        g_den[(size_t)z * (BB * NN * HH) + (size_t)(b * NN + na + 1) * HH + head] = denb;
    }
}

// ---------------- Kernel D: combine partials, normalize ----------------
__global__ void __launch_bounds__(256) k_combine(float* __restrict__ out) {
    int i4 = blockIdx.x * 256 + threadIdx.x;   // float4 index over B*N*F/4
    int bn = i4 >> 5;
    int head = (i4 >> 3) & 3;
    float sx = 0.f, sy = 0.f, sz = 0.f, sw = 0.f, den = 0.f;
    #pragma unroll
    for (int zz = 0; zz < MSPLIT; zz++) {
        float4 v = ((const float4*)(g_num + (size_t)zz * BB * NN * FF))[i4];
        sx += v.x; sy += v.y; sz += v.z; sw += v.w;
        den += g_den[(size_t)zz * BB * NN * HH + (size_t)bn * HH + head];
    }
    float inv = 1.f / den;
    ((float4*)out)[i4] = make_float4(sx * inv, sy * inv, sz * inv, sw * inv);
}

// ---------------- launch ----------------
extern "C" void kernel_launch(void* const* d_in, const int* in_sizes, int n_in,
                              void* d_out, int out_size) {
    const float* x     = (const float*)d_in[0];
    const int*   adj   = (const int*)d_in[1];
    const float* W     = (const float*)d_in[2];
    const float* a_src = (const float*)d_in[3];
    const float* a_dst = (const float*)d_in[4];
    float* out = (float*)d_out;

    cudaFuncSetAttribute(k_gemm, cudaFuncAttributeMaxDynamicSharedMemorySize, A_SMEM);
    cudaFuncSetAttribute(k_attn, cudaFuncAttributeMaxDynamicSharedMemorySize, C_SMEM);

    k_gemm<<<(BB * NN) / 64, 256, A_SMEM>>>(x, W);
    k_edge<<<(BB * NN * HH) / 256, 256>>>(a_src, a_dst);
    dim3 gC(NN / CROWS, BB, MSPLIT);
    k_attn<<<gC, 256, C_SMEM>>>(adj);
    k_combine<<<(BB * NN * FF / 4) / 256, 256>>>(out);
}

// round 5
// speedup vs baseline: 1.0065x; 1.0065x over previous
#include <cuda_runtime.h>
#include <cmath>

#define BB 4
#define NN 2048
#define FF 128
#define HH 4
#define DD 32
#define MSPLIT 8
#define CROWS 64
#define MT 64

// ---------------- scratch (no allocations allowed) ----------------
__device__ float  g_h[BB * NN * FF];                 // 4 MB: h = x @ W^T
__device__ float4 g_src[BB * NN * HH];               // (e_src, exp(e_src), exp(0.2 e_src), 0)
__device__ float4 g_dst[BB * NN * HH];               // (e_dst, exp(e_dst), exp(0.2 e_dst), 0)
__device__ float  g_num[MSPLIT * BB * NN * FF];      // 33.5 MB partial numerators
__device__ float  g_den[MSPLIT * BB * NN * HH];      // partial denominators

// ---------------- Kernel A: h = x @ W^T  (8192 x 128 @ 128 x 128) ----------------
// 64 rows per CTA, 256 threads. W (128x132-padded) + x tile (64x132-padded) in smem.
// Thread (r = tid>>2, c = tid&3) computes outputs o = 4k + c, k = 0..31.
#define A_SMEM ((128 * 132 + 64 * 132) * 4)

__global__ void __launch_bounds__(256) k_gemm(const float* __restrict__ x,
                                              const float* __restrict__ W) {
    extern __shared__ float sm[];
    float* shW = sm;              // [128][132]
    float* shX = sm + 128 * 132;  // [64][132]
    const int tid = threadIdx.x;
    const int row0 = blockIdx.x * 64;

    #pragma unroll
    for (int t = 0; t < 16; t++) {                 // 128*32 float4 chunks
        int idx = tid + t * 256;
        int o = idx >> 5, i4 = idx & 31;
        float4 v = ((const float4*)W)[o * 32 + i4];
        *((float4*)(shW + o * 132 + 4 * i4)) = v;
    }
    #pragma unroll
    for (int t = 0; t < 8; t++) {                  // 64*32 float4 chunks
        int idx = tid + t * 256;
        int r = idx >> 5, i4 = idx & 31;
        float4 v = ((const float4*)x)[(size_t)(row0 + r) * 32 + i4];
        *((float4*)(shX + r * 132 + 4 * i4)) = v;
    }
    __syncthreads();

    const int r = tid >> 2, c = tid & 3;
    float acc[32];
    #pragma unroll
    for (int k = 0; k < 32; k++) acc[k] = 0.f;

    #pragma unroll 4
    for (int i4 = 0; i4 < 32; i4++) {
        float4 xv = *((const float4*)(shX + r * 132 + 4 * i4));
        #pragma unroll
        for (int k = 0; k < 32; k++) {
            int o = 4 * k + c;
            float4 wv = *((const float4*)(shW + o * 132 + 4 * i4));
            acc[k] = fmaf(xv.x, wv.x, acc[k]);
            acc[k] = fmaf(xv.y, wv.y, acc[k]);
            acc[k] = fmaf(xv.z, wv.z, acc[k]);
            acc[k] = fmaf(xv.w, wv.w, acc[k]);
        }
    }
    float* hrow = g_h + (size_t)(row0 + r) * FF;
    #pragma unroll
    for (int k = 0; k < 32; k++) hrow[4 * k + c] = acc[k];
}

// ---------------- Kernel B: per-(b,n,h) edge terms + factored exps ----------------
__global__ void __launch_bounds__(256) k_edge(const float* __restrict__ a_src,
                                              const float* __restrict__ a_dst) {
    int idx = blockIdx.x * 256 + threadIdx.x;      // (bn*H + h)
    if (idx >= BB * NN * HH) return;
    int h = idx & 3;
    int bn = idx >> 2;
    const float* hp = g_h + (size_t)bn * FF + h * DD;
    const float* as = a_src + h * DD;
    const float* ad = a_dst + h * DD;
    float es = 0.f, ed = 0.f;
    #pragma unroll
    for (int d = 0; d < DD; d++) {
        float v = hp[d];
        es = fmaf(v, as[d], es);
        ed = fmaf(v, ad[d], ed);
    }
    g_src[idx] = make_float4(es, expf(es), expf(0.2f * es), 0.f);
    g_dst[idx] = make_float4(ed, expf(ed), expf(0.2f * ed), 0.f);
}

// ---------------- Kernel C: fused masked-softmax aggregation (partials) ----------------
// grid (N/CROWS=32, B=4, MSPLIT=8), 256 threads.
// Thread (rg = tid>>3, c = tid&7) owns 2 rows x 16 cols. h tile is XOR-swizzled
// (chunk q stored at q ^ ((q>>3)&7)) so the stride-4-chunk read pattern per
// quarter-warp covers 8 distinct bank groups -> conflict-free LDS.128.
#define C_SMEM ((MT * FF + MT * HH * 4 + CROWS * (MT + 1)) * 4)

__global__ void __launch_bounds__(256) k_attn(const int* __restrict__ adj) {
    extern __shared__ float sm[];
    float*  sh_h   = sm;                          // [MT][128] swizzled
    float4* sh_e   = (float4*)(sm + MT * FF);     // [MT][HH]
    float*  sh_adj = sm + MT * FF + MT * HH * 4;  // [CROWS][MT+1]

    const int tid  = threadIdx.x;
    const int c    = tid & 7;
    const int rg   = tid >> 3;
    const int b    = blockIdx.y;
    const int z    = blockIdx.z;
    const int n0   = blockIdx.x * CROWS;
    const int na   = n0 + 2 * rg;
    const int head = c >> 1;

    const float4 spa = g_src[(size_t)(b * NN + na) * HH + head];
    const float4 spb = g_src[(size_t)(b * NN + na + 1) * HH + head];

    float acc[32];
    #pragma unroll
    for (int k = 0; k < 32; k++) acc[k] = 0.f;
    float dena = 0.f, denb = 0.f;

    const float4* hbase = (const float4*)(g_h + (size_t)b * NN * FF);
    const float4* ebase = g_dst + (size_t)b * NN * HH;

    const int m_begin = z * (NN / MSPLIT);
    const int m_end   = m_begin + (NN / MSPLIT);

    for (int m0 = m_begin; m0 < m_end; m0 += MT) {
        __syncthreads();
        // h tile: 2048 float4 chunks, swizzled placement
        #pragma unroll
        for (int t = 0; t < 8; t++) {
            int gidx = tid + t * 256;
            int j = gidx >> 5;
            int q = gidx & 31;
            int qs = q ^ ((q >> 3) & 7);
            ((float4*)sh_h)[j * 32 + qs] = hbase[(size_t)m0 * 32 + gidx];
        }
        // e_dst tile: [j][h] float4, 256 chunks
        sh_e[tid] = ebase[m0 * HH + tid];
        // adj tile (as float), padded rows to kill bank conflicts
        #pragma unroll
        for (int t = 0; t < 16; t++) {
            int gi = tid + t * 256;
            int rr = gi >> 6;
            int jj = gi & 63;
            sh_adj[rr * (MT + 1) + jj] =
                (float)adj[(size_t)(n0 + rr) * NN + m0 + jj];
        }
        __syncthreads();

        #pragma unroll 2
        for (int j = 0; j < MT; j++) {
            float4 ep = sh_e[j * HH + head];
            float aja = sh_adj[(2 * rg) * (MT + 1) + j];
            float ajb = sh_adj[(2 * rg + 1) * (MT + 1) + j];
            float za = spa.x + ep.x;
            float zb = spb.x + ep.x;
            float wa = ((za > 0.f) ? spa.y * ep.y : spa.z * ep.z) * aja;
            float wb = ((zb > 0.f) ? spb.y * ep.y : spb.z * ep.z) * ajb;
            dena += wa;
            denb += wb;
            #pragma unroll
            for (int s = 0; s < 4; s++) {
                int q = 4 * c + s;
                int qs = q ^ ((q >> 3) & 7);
                float4 hv = ((const float4*)sh_h)[j * 32 + qs];
                acc[4 * s + 0] = fmaf(wa, hv.x, acc[4 * s + 0]);
                acc[4 * s + 1] = fmaf(wa, hv.y, acc[4 * s + 1]);
                acc[4 * s + 2] = fmaf(wa, hv.z, acc[4 * s + 2]);
                acc[4 * s + 3] = fmaf(wa, hv.w, acc[4 * s + 3]);
                acc[16 + 4 * s + 0] = fmaf(wb, hv.x, acc[16 + 4 * s + 0]);
                acc[16 + 4 * s + 1] = fmaf(wb, hv.y, acc[16 + 4 * s + 1]);
                acc[16 + 4 * s + 2] = fmaf(wb, hv.z, acc[16 + 4 * s + 2]);
                acc[16 + 4 * s + 3] = fmaf(wb, hv.w, acc[16 + 4 * s + 3]);
            }
        }
    }

    size_t obase = (size_t)z * (BB * NN * FF);
    float4* numa = (float4*)(g_num + obase + (size_t)(b * NN + na) * FF + 16 * c);
    float4* numb = (float4*)(g_num + obase + (size_t)(b * NN + na + 1) * FF + 16 * c);
    #pragma unroll
    for (int s = 0; s < 4; s++) {
        numa[s] = make_float4(acc[4 * s], acc[4 * s + 1], acc[4 * s + 2], acc[4 * s + 3]);
        numb[s] = make_float4(acc[16 + 4 * s], acc[16 + 4 * s + 1],
                              acc[16 + 4 * s + 2], acc[16 + 4 * s + 3]);
    }
    if ((c & 1) == 0) {
        g_den[(size_t)z * (BB * NN * HH) + (size_t)(b * NN + na) * HH + head]     = dena;
        g_den[(size_t)z * (BB * NN * HH) + (size_t)(b * NN + na + 1) * HH + head] = denb;
    }
}

// ---------------- Kernel D: combine partials, normalize ----------------
__global__ void __launch_bounds__(256) k_combine(float* __restrict__ out) {
    int i4 = blockIdx.x * 256 + threadIdx.x;   // float4 index over B*N*F/4
    int bn = i4 >> 5;
    int head = (i4 >> 3) & 3;
    float sx = 0.f, sy = 0.f, sz = 0.f, sw = 0.f, den = 0.f;
    #pragma unroll
    for (int zz = 0; zz < MSPLIT; zz++) {
        float4 v = ((const float4*)(g_num + (size_t)zz * BB * NN * FF))[i4];
        sx += v.x; sy += v.y; sz += v.z; sw += v.w;
        den += g_den[(size_t)zz * BB * NN * HH + (size_t)bn * HH + head];
    }
    float inv = 1.f / den;
    ((float4*)out)[i4] = make_float4(sx * inv, sy * inv, sz * inv, sw * inv);
}

// ---------------- launch ----------------
extern "C" void kernel_launch(void* const* d_in, const int* in_sizes, int n_in,
                              void* d_out, int out_size) {
    const float* x     = (const float*)d_in[0];
    const int*   adj   = (const int*)d_in[1];
    const float* W     = (const float*)d_in[2];
    const float* a_src = (const float*)d_in[3];
    const float* a_dst = (const float*)d_in[4];
    float* out = (float*)d_out;

    cudaFuncSetAttribute(k_gemm, cudaFuncAttributeMaxDynamicSharedMemorySize, A_SMEM);
    cudaFuncSetAttribute(k_attn, cudaFuncAttributeMaxDynamicSharedMemorySize, C_SMEM);

    k_gemm<<<(BB * NN) / 64, 256, A_SMEM>>>(x, W);
    k_edge<<<(BB * NN * HH) / 256, 256>>>(a_src, a_dst);
    dim3 gC(NN / CROWS, BB, MSPLIT);
    k_attn<<<gC, 256, C_SMEM>>>(adj);
    k_combine<<<(BB * NN * FF / 4) / 256, 256>>>(out);
}